// round 15
// baseline (speedup 1.0000x reference)
#include <cuda_runtime.h>
#include <cuda_fp16.h>
#include <mma.h>
#include <cstdint>

using namespace nvcuda;

// ---------------- static scratch (no allocations allowed) ----------------
#define MAXN 100000
#define MAXE 3200000
#define MAXG 256

__device__ __half g_h16T[(size_t)MAXN * 128];  // fp16 ping (u-form features)
__device__ __half g_h16U[(size_t)MAXN * 128];  // fp16 pong
__device__ float  g_bufA[(size_t)MAXN * 128];  // prop outputs (fp32, GEMM inputs)
__device__ float  g_bufB[(size_t)MAXN * 64];   // SG linear out (fp32, pooled)
__device__ float  g_deg[MAXN];
__device__ float  g_dinv[MAXN];
__device__ int    g_rowptr[MAXN + 1];
__device__ int    g_tmp[MAXN];
__device__ int    g_sums[256];
__device__ int    g_fill[MAXN];
__device__ int    g_srcs[MAXE];  // dst-sorted src indices (4B/edge)

static inline int cdiv(long long a, int b) { return (int)((a + b - 1) / b); }

// ---------------- degree prep ----------------
__global__ void deg_init_kernel(float* __restrict__ deg, int* __restrict__ fill, int N) {
    int i = blockIdx.x * blockDim.x + threadIdx.x;
    if (i < N) { deg[i] = 1.0f; fill[i] = 0; }  // self loop
}

__global__ void deg_accum_kernel(const int* __restrict__ dst, float* __restrict__ deg, int E) {
    int e = blockIdx.x * blockDim.x + threadIdx.x;
    if (e < E) atomicAdd(&deg[dst[e]], 1.0f);
}

// ---------------- CSR build: scan of in-degree (excl self loops) + fused dinv ------------
__global__ void scan_chunk_kernel(const float* __restrict__ deg, int* __restrict__ excl,
                                  int* __restrict__ sums, float* __restrict__ dinv, int N) {
    __shared__ int sh[1024];
    int i = blockIdx.x * 1024 + threadIdx.x;
    int v = 0;
    if (i < N) {
        float d = deg[i];
        v = (int)d - 1;
        dinv[i] = rsqrtf(d);
    }
    sh[threadIdx.x] = v;
    __syncthreads();
    for (int off = 1; off < 1024; off <<= 1) {
        int add = (threadIdx.x >= off) ? sh[threadIdx.x - off] : 0;
        __syncthreads();
        sh[threadIdx.x] += add;
        __syncthreads();
    }
    if (i < N) excl[i] = sh[threadIdx.x] - v;
    if (threadIdx.x == 1023) sums[blockIdx.x] = sh[1023];
}

// parallel exclusive scan of chunk sums (nchunks <= 256), one block
__global__ void scan_sums_kernel(int* __restrict__ sums, int nchunks) {
    __shared__ int sh[256];
    int t = threadIdx.x;
    int v = (t < nchunks) ? sums[t] : 0;
    sh[t] = v;
    __syncthreads();
    for (int off = 1; off < 256; off <<= 1) {
        int add = (t >= off) ? sh[t - off] : 0;
        __syncthreads();
        sh[t] += add;
        __syncthreads();
    }
    if (t < nchunks) sums[t] = sh[t] - v;  // exclusive
}

__global__ void finalize_rowptr_kernel(const int* __restrict__ excl, const int* __restrict__ sums,
                                       int* __restrict__ rp, int N, int E) {
    int i = blockIdx.x * blockDim.x + threadIdx.x;
    if (i < N) rp[i] = excl[i] + sums[i >> 10];
    if (i == 0) rp[N] = E;
}

__global__ void scatter_kernel(const int* __restrict__ src, const int* __restrict__ dst,
                               const int* __restrict__ rp, int* __restrict__ fill,
                               int* __restrict__ srcs, int E) {
    int e = blockIdx.x * blockDim.x + threadIdx.x;
    if (e >= E) return;
    int d = dst[e];
    int pos = rp[d] + atomicAdd(&fill[d], 1);
    srcs[pos] = src[e];
}

// ---------------- split-fp16 tensor-core GEMM (3x HMMA, ~fp32 precision) ----------------
// OUT[N,DOUT] = act(A)[N,DIN] @ W[DIN,DOUT]; A fp32, split hi/lo at staging.
// If dscale != nullptr, output row scaled by dscale[row] (u-form for props).
template <int DIN, int DOUT, bool RELU_IN, bool OUT_HALF>
__global__ __launch_bounds__(256) void gemm_tc16_kernel(const float* __restrict__ A,
                                                        const float* __restrict__ W,
                                                        void* __restrict__ outv,
                                                        const float* __restrict__ dscale,
                                                        int N) {
    constexpr int TR = (DOUT == 128) ? 64 : 128;
    constexpr int KC = 32;
    constexpr int AH = KC + 8;
    constexpr int WHD = DOUT + 8;
    constexpr int WP = DOUT + 4;
    constexpr int WC = DOUT / 32;
    constexpr int NT = 256;
    constexpr int B_AH = TR * AH * 2;
    constexpr int B_WH = KC * WHD * 2;
    constexpr int B_TILES = 2 * B_AH + 2 * B_WH;
    constexpr int B_STAGE = TR * WP * 4;
    constexpr int SMB = (B_TILES > B_STAGE) ? B_TILES : B_STAGE;
    __shared__ __align__(16) char smraw[SMB];
    __half* Ah = (__half*)smraw;
    __half* Al = (__half*)(smraw + B_AH);
    __half* Wh = (__half*)(smraw + 2 * B_AH);
    __half* Wl = (__half*)(smraw + 2 * B_AH + B_WH);

    const int tid = threadIdx.x;
    const int wid = tid >> 5;
    const int wr = wid / WC;
    const int wc = wid % WC;
    const int rbase = blockIdx.x * TR;

    wmma::fragment<wmma::accumulator, 16, 16, 16, float> c[2][2];
#pragma unroll
    for (int r = 0; r < 2; r++)
#pragma unroll
        for (int j = 0; j < 2; j++) wmma::fill_fragment(c[r][j], 0.0f);

    for (int k0 = 0; k0 < DIN; k0 += KC) {
        for (int idx = tid; idx < TR * KC / 4; idx += NT) {
            int r = idx / (KC / 4);
            int c4 = (idx % (KC / 4)) * 4;
            float4 v = make_float4(0.f, 0.f, 0.f, 0.f);
            int gr = rbase + r;
            if (gr < N) v = *(const float4*)(A + (size_t)gr * DIN + k0 + c4);
            if (RELU_IN) {
                v.x = fmaxf(v.x, 0.f); v.y = fmaxf(v.y, 0.f);
                v.z = fmaxf(v.z, 0.f); v.w = fmaxf(v.w, 0.f);
            }
            __half hx = __float2half_rn(v.x), hy = __float2half_rn(v.y);
            __half hz = __float2half_rn(v.z), hw = __float2half_rn(v.w);
            __half lx = __float2half_rn(v.x - __half2float(hx));
            __half ly = __float2half_rn(v.y - __half2float(hy));
            __half lz = __float2half_rn(v.z - __half2float(hz));
            __half lw = __float2half_rn(v.w - __half2float(hw));
            *(__half2*)(Ah + r * AH + c4) = __halves2half2(hx, hy);
            *(__half2*)(Ah + r * AH + c4 + 2) = __halves2half2(hz, hw);
            *(__half2*)(Al + r * AH + c4) = __halves2half2(lx, ly);
            *(__half2*)(Al + r * AH + c4 + 2) = __halves2half2(lz, lw);
        }
        for (int idx = tid; idx < KC * DOUT / 4; idx += NT) {
            int r = idx / (DOUT / 4);
            int c4 = (idx % (DOUT / 4)) * 4;
            float4 v = *(const float4*)(W + (size_t)(k0 + r) * DOUT + c4);
            __half hx = __float2half_rn(v.x), hy = __float2half_rn(v.y);
            __half hz = __float2half_rn(v.z), hw = __float2half_rn(v.w);
            __half lx = __float2half_rn(v.x - __half2float(hx));
            __half ly = __float2half_rn(v.y - __half2float(hy));
            __half lz = __float2half_rn(v.z - __half2float(hz));
            __half lw = __float2half_rn(v.w - __half2float(hw));
            *(__half2*)(Wh + r * WHD + c4) = __halves2half2(hx, hy);
            *(__half2*)(Wh + r * WHD + c4 + 2) = __halves2half2(hz, hw);
            *(__half2*)(Wl + r * WHD + c4) = __halves2half2(lx, ly);
            *(__half2*)(Wl + r * WHD + c4 + 2) = __halves2half2(lz, lw);
        }
        __syncthreads();

#pragma unroll
        for (int ks = 0; ks < KC; ks += 16) {
            wmma::fragment<wmma::matrix_a, 16, 16, 16, __half, wmma::row_major> ah[2], al[2];
            wmma::fragment<wmma::matrix_b, 16, 16, 16, __half, wmma::row_major> bh[2], bl[2];
#pragma unroll
            for (int r = 0; r < 2; r++) {
                wmma::load_matrix_sync(ah[r], Ah + (wr * 32 + r * 16) * AH + ks, AH);
                wmma::load_matrix_sync(al[r], Al + (wr * 32 + r * 16) * AH + ks, AH);
            }
#pragma unroll
            for (int j = 0; j < 2; j++) {
                wmma::load_matrix_sync(bh[j], Wh + ks * WHD + wc * 32 + j * 16, WHD);
                wmma::load_matrix_sync(bl[j], Wl + ks * WHD + wc * 32 + j * 16, WHD);
            }
#pragma unroll
            for (int r = 0; r < 2; r++)
#pragma unroll
                for (int j = 0; j < 2; j++) {
                    wmma::mma_sync(c[r][j], al[r], bh[j], c[r][j]);
                    wmma::mma_sync(c[r][j], ah[r], bl[j], c[r][j]);
                    wmma::mma_sync(c[r][j], ah[r], bh[j], c[r][j]);
                }
        }
        __syncthreads();
    }

    float* stage = (float*)smraw;
#pragma unroll
    for (int r = 0; r < 2; r++)
#pragma unroll
        for (int j = 0; j < 2; j++)
            wmma::store_matrix_sync(stage + (wr * 32 + r * 16) * WP + wc * 32 + j * 16,
                                    c[r][j], WP, wmma::mem_row_major);
    __syncthreads();

    for (int idx = tid; idx < TR * DOUT / 4; idx += NT) {
        int r = idx / (DOUT / 4);
        int c4 = (idx % (DOUT / 4)) * 4;
        int gr = rbase + r;
        if (gr >= N) continue;
        float4 v = *(float4*)(stage + r * WP + c4);
        float sc = dscale ? dscale[gr] : 1.0f;
        v.x *= sc; v.y *= sc; v.z *= sc; v.w *= sc;
        if constexpr (OUT_HALF) {
            __half* out = (__half*)outv;
            __half2 ha = __floats2half2_rn(v.x, v.y);
            __half2 hb = __floats2half2_rn(v.z, v.w);
            uint2 u;
            u.x = *(unsigned*)&ha;
            u.y = *(unsigned*)&hb;
            *(uint2*)(out + (size_t)gr * DOUT + c4) = u;
        } else {
            *(float4*)((float*)outv + (size_t)gr * DOUT + c4) = v;
        }
    }
}

// ---------------- CSR propagate on u-form features ----------------
// u[s] = dinv[s]*t[s] stored fp16. out_i = dinv_i*(act(u_i) + sum_j act(u_src_j)) + b.
// SCALE_OUT: write fp16(dinv_i * out_i) (u-form for next prop); else fp32 plain.
// srcs loads vectorized: peel to 16B alignment, then int4 pairs in the 8-unroll.
template <int D, bool RELU, bool SCALE_OUT>
__global__ void csr_prop_u_kernel(const __half* __restrict__ t, void* __restrict__ outv,
                                  const int* __restrict__ srcs, const int* __restrict__ rp,
                                  const float* __restrict__ dinv, const float* __restrict__ bias,
                                  int N) {
    constexpr int H = D / 32;
    int warp = (blockIdx.x * blockDim.x + threadIdx.x) >> 5;
    int lane = threadIdx.x & 31;
    if (warp >= N) return;
    const int i = warp;
    int j0 = rp[i], j1 = rp[i + 1];

    auto load_row = [&](int s, float* f) {
        if constexpr (H == 2) {
            unsigned u = *((const unsigned*)(t + (size_t)s * D) + lane);
            float2 fv = __half22float2(*(__half2*)&u);
            f[0] = fv.x; f[1] = fv.y;
        } else {
            uint2 u = *((const uint2*)(t + (size_t)s * D) + lane);
            float2 fa = __half22float2(*(__half2*)&u.x);
            float2 fb = __half22float2(*(__half2*)&u.y);
            f[0] = fa.x; f[1] = fa.y; f[2] = fb.x; f[3] = fb.y;
        }
    };

    // self row load hoisted: overlaps with the gather stream
    float self[H];
    load_row(i, self);

    float acc[H];
#pragma unroll
    for (int v = 0; v < H; v++) acc[v] = 0.f;

    auto add_edge = [&](int s) {
        float a0[H];
        load_row(s, a0);
#pragma unroll
        for (int v = 0; v < H; v++) acc[v] += RELU ? fmaxf(a0[v], 0.f) : a0[v];
    };

    int j = j0;
    // peel to 16B alignment of srcs+j
    int mis = j & 3;
    if (mis) {
        int cnt = 4 - mis;
        if (cnt > j1 - j) cnt = j1 - j;
        for (int u = 0; u < cnt; u++) add_edge(srcs[j + u]);
        j += cnt;
    }
    // main loop: 8 edges per iter via 2 x int4 loads
    for (; j + 7 < j1; j += 8) {
        int4 sA = *(const int4*)(srcs + j);
        int4 sB = *(const int4*)(srcs + j + 4);
        int s[8] = {sA.x, sA.y, sA.z, sA.w, sB.x, sB.y, sB.z, sB.w};
        float a[8][H > 2 ? 4 : 2];
#pragma unroll
        for (int u = 0; u < 8; u++) load_row(s[u], a[u]);
#pragma unroll
        for (int u = 0; u < 8; u++)
#pragma unroll
            for (int v = 0; v < H; v++)
                acc[v] += RELU ? fmaxf(a[u][v], 0.f) : a[u][v];
    }
    // 4-edge step (still aligned)
    if (j + 3 < j1) {
        int4 sA = *(const int4*)(srcs + j);
        int s[4] = {sA.x, sA.y, sA.z, sA.w};
        float a[4][H > 2 ? 4 : 2];
#pragma unroll
        for (int u = 0; u < 4; u++) load_row(s[u], a[u]);
#pragma unroll
        for (int u = 0; u < 4; u++)
#pragma unroll
            for (int v = 0; v < H; v++)
                acc[v] += RELU ? fmaxf(a[u][v], 0.f) : a[u][v];
        j += 4;
    }
    for (; j < j1; j++) add_edge(srcs[j]);

    float dv = dinv[i];
    float o[H];
#pragma unroll
    for (int v = 0; v < H; v++) {
        float sv = RELU ? fmaxf(self[v], 0.f) : self[v];
        float b = bias ? bias[lane * H + v] : 0.f;
        o[v] = fmaf(dv, acc[v] + sv, b);
        if (SCALE_OUT) o[v] *= dv;
    }

    if constexpr (SCALE_OUT) {
        __half* out = (__half*)outv;
        if constexpr (H == 2) {
            __half2 h = __floats2half2_rn(o[0], o[1]);
            *((unsigned*)(out + (size_t)i * D) + lane) = *(unsigned*)&h;
        } else {
            __half2 ha = __floats2half2_rn(o[0], o[1]);
            __half2 hb = __floats2half2_rn(o[2], o[3]);
            uint2 u;
            u.x = *(unsigned*)&ha;
            u.y = *(unsigned*)&hb;
            *((uint2*)(out + (size_t)i * D) + lane) = u;
        }
    } else {
        float* out = (float*)outv;
        if constexpr (H == 2) {
            *(float2*)(out + (size_t)i * D + lane * 2) = make_float2(o[0], o[1]);
        } else {
            *(float4*)(out + (size_t)i * D + lane * 4) = make_float4(o[0], o[1], o[2], o[3]);
        }
    }
}

// ---------------- fused segment-bounds + max-pool + head MLP (one block per graph) -------
__global__ void pool_head_kernel(const float* __restrict__ z, const int* __restrict__ batch,
                                 const float* __restrict__ sgb,
                                 const float* __restrict__ fc1w, const float* __restrict__ fc1b,
                                 const float* __restrict__ fc2w, const float* __restrict__ fc2b,
                                 const float* __restrict__ cpdw, const float* __restrict__ cpdb,
                                 const float* __restrict__ combw, const float* __restrict__ combb,
                                 float* __restrict__ out, int N, int G) {
    int g = blockIdx.x;
    int t = threadIdx.x;  // 256
    int tx = t & 63;
    int ty = t >> 6;      // 0..3
    __shared__ int se[2];
    __shared__ float sm[4][64];
    __shared__ float z0[64], z1[32], z2[16];

    if (t < 2) {
        int target = g + t;
        int lo = 0, hi = N;
        while (lo < hi) {
            int mid = (lo + hi) >> 1;
            if (batch[mid] < target) lo = mid + 1; else hi = mid;
        }
        se[t] = lo;
    }
    __syncthreads();
    int s = se[0], e = se[1];

    float m = -3.4028235e38f;
    for (int i = s + ty; i < e; i += 4) m = fmaxf(m, z[(size_t)i * 64 + tx]);
    sm[ty][tx] = m;
    __syncthreads();
    if (ty == 0)
        z0[tx] = fmaxf(fmaxf(sm[0][tx], sm[1][tx]), fmaxf(sm[2][tx], sm[3][tx])) + sgb[tx];
    __syncthreads();

    if (t < 32) {
        float sacc = fc1b[t];
        for (int k = 0; k < 64; k++) sacc = fmaf(z0[k], fc1w[k * 32 + t], sacc);
        z1[t] = fmaxf(sacc, 0.f);
    }
    __syncthreads();
    if (t < 16) {
        float sacc = fc2b[t];
        for (int k = 0; k < 32; k++) sacc = fmaf(z1[k], fc2w[k * 16 + t], sacc);
        z2[t] = fmaxf(sacc, 0.f);
    }
    __syncthreads();
    if (t == 0) {
        float sacc = cpdb[0];
        for (int k = 0; k < 16; k++) sacc = fmaf(z2[k], cpdw[k], sacc);
        out[g] = sacc;
    }
    if (t == 1) {
        float sacc = combb[0];
        for (int k = 0; k < 16; k++) sacc = fmaf(z2[k], combw[k], sacc);
        out[G + g] = sacc;
    }
}

// ---------------- host side ----------------
extern "C" void kernel_launch(void* const* d_in, const int* in_sizes, int n_in,
                              void* d_out, int out_size) {
    const float* x     = (const float*)d_in[0];
    const int*   ei    = (const int*)d_in[1];
    const int*   batch = (const int*)d_in[2];
    const float* enc_w1 = (const float*)d_in[3];
    const float* enc_b1 = (const float*)d_in[4];
    const float* enc_w2 = (const float*)d_in[5];
    const float* enc_b2 = (const float*)d_in[6];
    const float* w1 = (const float*)d_in[7];
    const float* b1 = (const float*)d_in[8];
    const float* w2 = (const float*)d_in[9];
    const float* b2 = (const float*)d_in[10];
    const float* w3 = (const float*)d_in[11];
    const float* b3 = (const float*)d_in[12];
    const float* sg_w = (const float*)d_in[13];
    const float* sg_b = (const float*)d_in[14];
    const float* fc1_w = (const float*)d_in[15];
    const float* fc1_b = (const float*)d_in[16];
    const float* fc2_w = (const float*)d_in[17];
    const float* fc2_b = (const float*)d_in[18];
    const float* cpd_w = (const float*)d_in[19];
    const float* cpd_b = (const float*)d_in[20];
    const float* comb_w = (const float*)d_in[21];
    const float* comb_b = (const float*)d_in[22];
    float* out = (float*)d_out;

    const int N = in_sizes[0] / 128;
    const int E = in_sizes[1] / 2;
    const int G = out_size / 2;

    const int* src = ei;
    const int* dst = ei + E;

    void *pT16, *pU16, *pA, *pB, *pDeg, *pDinv, *pRp, *pTmp, *pSums, *pFill, *pSrcs;
    cudaGetSymbolAddress(&pT16, g_h16T);
    cudaGetSymbolAddress(&pU16, g_h16U);
    cudaGetSymbolAddress(&pA, g_bufA);
    cudaGetSymbolAddress(&pB, g_bufB);
    cudaGetSymbolAddress(&pDeg, g_deg);
    cudaGetSymbolAddress(&pDinv, g_dinv);
    cudaGetSymbolAddress(&pRp, g_rowptr);
    cudaGetSymbolAddress(&pTmp, g_tmp);
    cudaGetSymbolAddress(&pSums, g_sums);
    cudaGetSymbolAddress(&pFill, g_fill);
    cudaGetSymbolAddress(&pSrcs, g_srcs);
    __half* T16 = (__half*)pT16;
    __half* U16 = (__half*)pU16;
    float* bufA = (float*)pA;
    float* bufB = (float*)pB;
    float* deg = (float*)pDeg;
    float* dinv = (float*)pDinv;
    int* rp = (int*)pRp;
    int* tmp = (int*)pTmp;
    int* sums = (int*)pSums;
    int* fill = (int*)pFill;
    int* srcs = (int*)pSrcs;

    const int TB = 256;
    const int nchunks = cdiv(N, 1024);

    // ---- degree / dinv / CSR build ----
    deg_init_kernel<<<cdiv(N, TB), TB>>>(deg, fill, N);
    deg_accum_kernel<<<cdiv(E, TB), TB>>>(dst, deg, E);
    scan_chunk_kernel<<<nchunks, 1024>>>(deg, tmp, sums, dinv, N);
    scan_sums_kernel<<<1, 256>>>(sums, nchunks);
    finalize_rowptr_kernel<<<cdiv(N, TB), TB>>>(tmp, sums, rp, N, E);
    scatter_kernel<<<cdiv(E, TB), TB>>>(src, dst, rp, fill, srcs, E);

    const int propGrid = cdiv(N, 8);  // warp per node, 8 warps/block

    // ---- encoder layer 1 (GEMM writes u-form: dinv * (x@W)) ----
    gemm_tc16_kernel<128, 128, false, true><<<cdiv(N, 64), 256>>>(x, enc_w1, T16, dinv, N);
    csr_prop_u_kernel<128, false, false><<<propGrid, TB>>>(T16, bufA, srcs, rp, dinv, enc_b1, N);

    // ---- encoder layer 2 (relu fused into GEMM A-stage; u-form out) ----
    gemm_tc16_kernel<128, 64, true, true><<<cdiv(N, 128), 256>>>(bufA, enc_w2, T16, dinv, N);
    csr_prop_u_kernel<64, false, false><<<propGrid, TB>>>(T16, bufA, srcs, rp, dinv, enc_b2, N);

    // ---- conv1 (enc2 output NOT relu'd) ----
    gemm_tc16_kernel<64, 64, false, true><<<cdiv(N, 128), 256>>>(bufA, w1, T16, dinv, N);
    csr_prop_u_kernel<64, false, false><<<propGrid, TB>>>(T16, bufA, srcs, rp, dinv, b1, N);

    // ---- conv2 ----
    gemm_tc16_kernel<64, 64, true, true><<<cdiv(N, 128), 256>>>(bufA, w2, T16, dinv, N);
    csr_prop_u_kernel<64, false, false><<<propGrid, TB>>>(T16, bufA, srcs, rp, dinv, b2, N);

    // ---- conv3 (prop writes u-form fp16, pre-relu; relu fused into SG prop1) ----
    gemm_tc16_kernel<64, 64, true, true><<<cdiv(N, 128), 256>>>(bufA, w3, T16, dinv, N);
    csr_prop_u_kernel<64, false, true><<<propGrid, TB>>>(T16, U16, srcs, rp, dinv, b3, N);

    // ---- SGConv: 4 propagations (u-form chain, last writes plain fp32) ----
    csr_prop_u_kernel<64, true, true><<<propGrid, TB>>>(U16, T16, srcs, rp, dinv, nullptr, N);
    csr_prop_u_kernel<64, false, true><<<propGrid, TB>>>(T16, U16, srcs, rp, dinv, nullptr, N);
    csr_prop_u_kernel<64, false, true><<<propGrid, TB>>>(U16, T16, srcs, rp, dinv, nullptr, N);
    csr_prop_u_kernel<64, false, false><<<propGrid, TB>>>(T16, bufA, srcs, rp, dinv, nullptr, N);

    // ---- SG linear (bias folded past max-pool; fp32 out, no scale) ----
    gemm_tc16_kernel<64, 64, false, false><<<cdiv(N, 128), 256>>>(bufA, sg_w, bufB, nullptr, N);

    // ---- fused pool + head ----
    pool_head_kernel<<<G, 256>>>(bufB, batch, sg_b, fc1_w, fc1_b, fc2_w, fc2_b,
                                 cpd_w, cpd_b, comb_w, comb_b, out, N, G);
}

// round 16
// speedup vs baseline: 1.0084x; 1.0084x over previous
#include <cuda_runtime.h>
#include <cuda_fp16.h>
#include <mma.h>
#include <cstdint>

using namespace nvcuda;

// ---------------- static scratch (no allocations allowed) ----------------
#define MAXN 100000
#define MAXE 3200000
#define MAXG 256

__device__ __half g_h16T[(size_t)MAXN * 128];  // fp16 ping (u-form features)
__device__ __half g_h16U[(size_t)MAXN * 128];  // fp16 pong
__device__ float  g_bufA[(size_t)MAXN * 128];  // prop outputs (fp32, GEMM inputs)
__device__ float  g_bufB[(size_t)MAXN * 64];   // SG linear out (fp32, pooled)
__device__ float  g_deg[MAXN];
__device__ float  g_dinv[MAXN];
__device__ int    g_rowptr[MAXN + 1];
__device__ int    g_tmp[MAXN];
__device__ int    g_sums[256];
__device__ int    g_fill[MAXN];
__device__ int    g_srcs[MAXE];  // dst-sorted src indices (4B/edge)

static inline int cdiv(long long a, int b) { return (int)((a + b - 1) / b); }

// ---------------- degree prep ----------------
__global__ void deg_init_kernel(float* __restrict__ deg, int* __restrict__ fill, int N) {
    int i = blockIdx.x * blockDim.x + threadIdx.x;
    if (i < N) { deg[i] = 1.0f; fill[i] = 0; }  // self loop
}

__global__ void deg_accum_kernel(const int* __restrict__ dst, float* __restrict__ deg, int E) {
    int e = blockIdx.x * blockDim.x + threadIdx.x;
    if (e < E) atomicAdd(&deg[dst[e]], 1.0f);
}

// ---------------- CSR build: scan of in-degree (excl self loops) + fused dinv ------------
__global__ void scan_chunk_kernel(const float* __restrict__ deg, int* __restrict__ excl,
                                  int* __restrict__ sums, float* __restrict__ dinv, int N) {
    __shared__ int sh[1024];
    int i = blockIdx.x * 1024 + threadIdx.x;
    int v = 0;
    if (i < N) {
        float d = deg[i];
        v = (int)d - 1;
        dinv[i] = rsqrtf(d);
    }
    sh[threadIdx.x] = v;
    __syncthreads();
    for (int off = 1; off < 1024; off <<= 1) {
        int add = (threadIdx.x >= off) ? sh[threadIdx.x - off] : 0;
        __syncthreads();
        sh[threadIdx.x] += add;
        __syncthreads();
    }
    if (i < N) excl[i] = sh[threadIdx.x] - v;
    if (threadIdx.x == 1023) sums[blockIdx.x] = sh[1023];
}

// parallel exclusive scan of chunk sums (nchunks <= 256), one block
__global__ void scan_sums_kernel(int* __restrict__ sums, int nchunks) {
    __shared__ int sh[256];
    int t = threadIdx.x;
    int v = (t < nchunks) ? sums[t] : 0;
    sh[t] = v;
    __syncthreads();
    for (int off = 1; off < 256; off <<= 1) {
        int add = (t >= off) ? sh[t - off] : 0;
        __syncthreads();
        sh[t] += add;
        __syncthreads();
    }
    if (t < nchunks) sums[t] = sh[t] - v;  // exclusive
}

__global__ void finalize_rowptr_kernel(const int* __restrict__ excl, const int* __restrict__ sums,
                                       int* __restrict__ rp, int N, int E) {
    int i = blockIdx.x * blockDim.x + threadIdx.x;
    if (i < N) rp[i] = excl[i] + sums[i >> 10];
    if (i == 0) rp[N] = E;
}

__global__ void scatter_kernel(const int* __restrict__ src, const int* __restrict__ dst,
                               const int* __restrict__ rp, int* __restrict__ fill,
                               int* __restrict__ srcs, int E) {
    int e = blockIdx.x * blockDim.x + threadIdx.x;
    if (e >= E) return;
    int d = dst[e];
    int pos = rp[d] + atomicAdd(&fill[d], 1);
    srcs[pos] = src[e];
}

// ---------------- split-fp16 tensor-core GEMM (3x HMMA, ~fp32 precision) ----------------
// OUT[N,DOUT] = act(A)[N,DIN] @ W[DIN,DOUT]; A fp32, split hi/lo at staging.
// If dscale != nullptr, output row scaled by dscale[row] (u-form for props).
template <int DIN, int DOUT, bool RELU_IN, bool OUT_HALF>
__global__ __launch_bounds__(256) void gemm_tc16_kernel(const float* __restrict__ A,
                                                        const float* __restrict__ W,
                                                        void* __restrict__ outv,
                                                        const float* __restrict__ dscale,
                                                        int N) {
    constexpr int TR = (DOUT == 128) ? 64 : 128;
    constexpr int KC = 32;
    constexpr int AH = KC + 8;
    constexpr int WHD = DOUT + 8;
    constexpr int WP = DOUT + 4;
    constexpr int WC = DOUT / 32;
    constexpr int NT = 256;
    constexpr int B_AH = TR * AH * 2;
    constexpr int B_WH = KC * WHD * 2;
    constexpr int B_TILES = 2 * B_AH + 2 * B_WH;
    constexpr int B_STAGE = TR * WP * 4;
    constexpr int SMB = (B_TILES > B_STAGE) ? B_TILES : B_STAGE;
    __shared__ __align__(16) char smraw[SMB];
    __half* Ah = (__half*)smraw;
    __half* Al = (__half*)(smraw + B_AH);
    __half* Wh = (__half*)(smraw + 2 * B_AH);
    __half* Wl = (__half*)(smraw + 2 * B_AH + B_WH);

    const int tid = threadIdx.x;
    const int wid = tid >> 5;
    const int wr = wid / WC;
    const int wc = wid % WC;
    const int rbase = blockIdx.x * TR;

    wmma::fragment<wmma::accumulator, 16, 16, 16, float> c[2][2];
#pragma unroll
    for (int r = 0; r < 2; r++)
#pragma unroll
        for (int j = 0; j < 2; j++) wmma::fill_fragment(c[r][j], 0.0f);

    for (int k0 = 0; k0 < DIN; k0 += KC) {
        for (int idx = tid; idx < TR * KC / 4; idx += NT) {
            int r = idx / (KC / 4);
            int c4 = (idx % (KC / 4)) * 4;
            float4 v = make_float4(0.f, 0.f, 0.f, 0.f);
            int gr = rbase + r;
            if (gr < N) v = *(const float4*)(A + (size_t)gr * DIN + k0 + c4);
            if (RELU_IN) {
                v.x = fmaxf(v.x, 0.f); v.y = fmaxf(v.y, 0.f);
                v.z = fmaxf(v.z, 0.f); v.w = fmaxf(v.w, 0.f);
            }
            __half hx = __float2half_rn(v.x), hy = __float2half_rn(v.y);
            __half hz = __float2half_rn(v.z), hw = __float2half_rn(v.w);
            __half lx = __float2half_rn(v.x - __half2float(hx));
            __half ly = __float2half_rn(v.y - __half2float(hy));
            __half lz = __float2half_rn(v.z - __half2float(hz));
            __half lw = __float2half_rn(v.w - __half2float(hw));
            *(__half2*)(Ah + r * AH + c4) = __halves2half2(hx, hy);
            *(__half2*)(Ah + r * AH + c4 + 2) = __halves2half2(hz, hw);
            *(__half2*)(Al + r * AH + c4) = __halves2half2(lx, ly);
            *(__half2*)(Al + r * AH + c4 + 2) = __halves2half2(lz, lw);
        }
        for (int idx = tid; idx < KC * DOUT / 4; idx += NT) {
            int r = idx / (DOUT / 4);
            int c4 = (idx % (DOUT / 4)) * 4;
            float4 v = *(const float4*)(W + (size_t)(k0 + r) * DOUT + c4);
            __half hx = __float2half_rn(v.x), hy = __float2half_rn(v.y);
            __half hz = __float2half_rn(v.z), hw = __float2half_rn(v.w);
            __half lx = __float2half_rn(v.x - __half2float(hx));
            __half ly = __float2half_rn(v.y - __half2float(hy));
            __half lz = __float2half_rn(v.z - __half2float(hz));
            __half lw = __float2half_rn(v.w - __half2float(hw));
            *(__half2*)(Wh + r * WHD + c4) = __halves2half2(hx, hy);
            *(__half2*)(Wh + r * WHD + c4 + 2) = __halves2half2(hz, hw);
            *(__half2*)(Wl + r * WHD + c4) = __halves2half2(lx, ly);
            *(__half2*)(Wl + r * WHD + c4 + 2) = __halves2half2(lz, lw);
        }
        __syncthreads();

#pragma unroll
        for (int ks = 0; ks < KC; ks += 16) {
            wmma::fragment<wmma::matrix_a, 16, 16, 16, __half, wmma::row_major> ah[2], al[2];
            wmma::fragment<wmma::matrix_b, 16, 16, 16, __half, wmma::row_major> bh[2], bl[2];
#pragma unroll
            for (int r = 0; r < 2; r++) {
                wmma::load_matrix_sync(ah[r], Ah + (wr * 32 + r * 16) * AH + ks, AH);
                wmma::load_matrix_sync(al[r], Al + (wr * 32 + r * 16) * AH + ks, AH);
            }
#pragma unroll
            for (int j = 0; j < 2; j++) {
                wmma::load_matrix_sync(bh[j], Wh + ks * WHD + wc * 32 + j * 16, WHD);
                wmma::load_matrix_sync(bl[j], Wl + ks * WHD + wc * 32 + j * 16, WHD);
            }
#pragma unroll
            for (int r = 0; r < 2; r++)
#pragma unroll
                for (int j = 0; j < 2; j++) {
                    wmma::mma_sync(c[r][j], al[r], bh[j], c[r][j]);
                    wmma::mma_sync(c[r][j], ah[r], bl[j], c[r][j]);
                    wmma::mma_sync(c[r][j], ah[r], bh[j], c[r][j]);
                }
        }
        __syncthreads();
    }

    float* stage = (float*)smraw;
#pragma unroll
    for (int r = 0; r < 2; r++)
#pragma unroll
        for (int j = 0; j < 2; j++)
            wmma::store_matrix_sync(stage + (wr * 32 + r * 16) * WP + wc * 32 + j * 16,
                                    c[r][j], WP, wmma::mem_row_major);
    __syncthreads();

    for (int idx = tid; idx < TR * DOUT / 4; idx += NT) {
        int r = idx / (DOUT / 4);
        int c4 = (idx % (DOUT / 4)) * 4;
        int gr = rbase + r;
        if (gr >= N) continue;
        float4 v = *(float4*)(stage + r * WP + c4);
        float sc = dscale ? dscale[gr] : 1.0f;
        v.x *= sc; v.y *= sc; v.z *= sc; v.w *= sc;
        if constexpr (OUT_HALF) {
            __half* out = (__half*)outv;
            __half2 ha = __floats2half2_rn(v.x, v.y);
            __half2 hb = __floats2half2_rn(v.z, v.w);
            uint2 u;
            u.x = *(unsigned*)&ha;
            u.y = *(unsigned*)&hb;
            *(uint2*)(out + (size_t)gr * DOUT + c4) = u;
        } else {
            *(float4*)((float*)outv + (size_t)gr * DOUT + c4) = v;
        }
    }
}

// ---------------- CSR propagate on u-form features (R14 version) ----------------
// u[s] = dinv[s]*t[s] stored fp16. out_i = dinv_i*(act(u_i) + sum_j act(u_src_j)) + b.
// SCALE_OUT: write fp16(dinv_i * out_i) (u-form for next prop); else fp32 plain.
template <int D, bool RELU, bool SCALE_OUT>
__global__ void csr_prop_u_kernel(const __half* __restrict__ t, void* __restrict__ outv,
                                  const int* __restrict__ srcs, const int* __restrict__ rp,
                                  const float* __restrict__ dinv, const float* __restrict__ bias,
                                  int N) {
    constexpr int H = D / 32;
    int warp = (blockIdx.x * blockDim.x + threadIdx.x) >> 5;
    int lane = threadIdx.x & 31;
    if (warp >= N) return;
    const int i = warp;
    int j0 = rp[i], j1 = rp[i + 1];

    float acc[H];
#pragma unroll
    for (int v = 0; v < H; v++) acc[v] = 0.f;

    auto load_row = [&](int s, float* f) {
        if constexpr (H == 2) {
            unsigned u = *((const unsigned*)(t + (size_t)s * D) + lane);
            float2 fv = __half22float2(*(__half2*)&u);
            f[0] = fv.x; f[1] = fv.y;
        } else {
            uint2 u = *((const uint2*)(t + (size_t)s * D) + lane);
            float2 fa = __half22float2(*(__half2*)&u.x);
            float2 fb = __half22float2(*(__half2*)&u.y);
            f[0] = fa.x; f[1] = fa.y; f[2] = fb.x; f[3] = fb.y;
        }
    };

    int j = j0;
    for (; j + 7 < j1; j += 8) {
        int s[8];
#pragma unroll
        for (int u = 0; u < 8; u++) s[u] = srcs[j + u];
        float a[8][H > 2 ? 4 : 2];
#pragma unroll
        for (int u = 0; u < 8; u++) load_row(s[u], a[u]);
#pragma unroll
        for (int u = 0; u < 8; u++)
#pragma unroll
            for (int v = 0; v < H; v++)
                acc[v] += RELU ? fmaxf(a[u][v], 0.f) : a[u][v];
    }
    for (; j + 1 < j1; j += 2) {
        int s0 = srcs[j], s1 = srcs[j + 1];
        float a0[H], a1[H];
        load_row(s0, a0);
        load_row(s1, a1);
#pragma unroll
        for (int v = 0; v < H; v++) {
            acc[v] += RELU ? fmaxf(a0[v], 0.f) : a0[v];
            acc[v] += RELU ? fmaxf(a1[v], 0.f) : a1[v];
        }
    }
    if (j < j1) {
        int s0 = srcs[j];
        float a0[H];
        load_row(s0, a0);
#pragma unroll
        for (int v = 0; v < H; v++) acc[v] += RELU ? fmaxf(a0[v], 0.f) : a0[v];
    }

    float dv = dinv[i];
    float self[H];
    load_row(i, self);
    float o[H];
#pragma unroll
    for (int v = 0; v < H; v++) {
        float sv = RELU ? fmaxf(self[v], 0.f) : self[v];
        float b = bias ? bias[lane * H + v] : 0.f;
        o[v] = fmaf(dv, acc[v] + sv, b);
        if (SCALE_OUT) o[v] *= dv;
    }

    if constexpr (SCALE_OUT) {
        __half* out = (__half*)outv;
        if constexpr (H == 2) {
            __half2 h = __floats2half2_rn(o[0], o[1]);
            *((unsigned*)(out + (size_t)i * D) + lane) = *(unsigned*)&h;
        } else {
            __half2 ha = __floats2half2_rn(o[0], o[1]);
            __half2 hb = __floats2half2_rn(o[2], o[3]);
            uint2 u;
            u.x = *(unsigned*)&ha;
            u.y = *(unsigned*)&hb;
            *((uint2*)(out + (size_t)i * D) + lane) = u;
        }
    } else {
        float* out = (float*)outv;
        if constexpr (H == 2) {
            *(float2*)(out + (size_t)i * D + lane * 2) = make_float2(o[0], o[1]);
        } else {
            *(float4*)(out + (size_t)i * D + lane * 4) = make_float4(o[0], o[1], o[2], o[3]);
        }
    }
}

// ---------------- fused segment-bounds + max-pool + head MLP (one block per graph) -------
__global__ void pool_head_kernel(const float* __restrict__ z, const int* __restrict__ batch,
                                 const float* __restrict__ sgb,
                                 const float* __restrict__ fc1w, const float* __restrict__ fc1b,
                                 const float* __restrict__ fc2w, const float* __restrict__ fc2b,
                                 const float* __restrict__ cpdw, const float* __restrict__ cpdb,
                                 const float* __restrict__ combw, const float* __restrict__ combb,
                                 float* __restrict__ out, int N, int G) {
    int g = blockIdx.x;
    int t = threadIdx.x;  // 256
    int tx = t & 63;
    int ty = t >> 6;      // 0..3
    __shared__ int se[2];
    __shared__ float sm[4][64];
    __shared__ float z0[64], z1[32], z2[16];

    if (t < 2) {
        int target = g + t;
        int lo = 0, hi = N;
        while (lo < hi) {
            int mid = (lo + hi) >> 1;
            if (batch[mid] < target) lo = mid + 1; else hi = mid;
        }
        se[t] = lo;
    }
    __syncthreads();
    int s = se[0], e = se[1];

    float m = -3.4028235e38f;
    for (int i = s + ty; i < e; i += 4) m = fmaxf(m, z[(size_t)i * 64 + tx]);
    sm[ty][tx] = m;
    __syncthreads();
    if (ty == 0)
        z0[tx] = fmaxf(fmaxf(sm[0][tx], sm[1][tx]), fmaxf(sm[2][tx], sm[3][tx])) + sgb[tx];
    __syncthreads();

    if (t < 32) {
        float sacc = fc1b[t];
        for (int k = 0; k < 64; k++) sacc = fmaf(z0[k], fc1w[k * 32 + t], sacc);
        z1[t] = fmaxf(sacc, 0.f);
    }
    __syncthreads();
    if (t < 16) {
        float sacc = fc2b[t];
        for (int k = 0; k < 32; k++) sacc = fmaf(z1[k], fc2w[k * 16 + t], sacc);
        z2[t] = fmaxf(sacc, 0.f);
    }
    __syncthreads();
    if (t == 0) {
        float sacc = cpdb[0];
        for (int k = 0; k < 16; k++) sacc = fmaf(z2[k], cpdw[k], sacc);
        out[g] = sacc;
    }
    if (t == 1) {
        float sacc = combb[0];
        for (int k = 0; k < 16; k++) sacc = fmaf(z2[k], combw[k], sacc);
        out[G + g] = sacc;
    }
}

// ---------------- host side ----------------
extern "C" void kernel_launch(void* const* d_in, const int* in_sizes, int n_in,
                              void* d_out, int out_size) {
    const float* x     = (const float*)d_in[0];
    const int*   ei    = (const int*)d_in[1];
    const int*   batch = (const int*)d_in[2];
    const float* enc_w1 = (const float*)d_in[3];
    const float* enc_b1 = (const float*)d_in[4];
    const float* enc_w2 = (const float*)d_in[5];
    const float* enc_b2 = (const float*)d_in[6];
    const float* w1 = (const float*)d_in[7];
    const float* b1 = (const float*)d_in[8];
    const float* w2 = (const float*)d_in[9];
    const float* b2 = (const float*)d_in[10];
    const float* w3 = (const float*)d_in[11];
    const float* b3 = (const float*)d_in[12];
    const float* sg_w = (const float*)d_in[13];
    const float* sg_b = (const float*)d_in[14];
    const float* fc1_w = (const float*)d_in[15];
    const float* fc1_b = (const float*)d_in[16];
    const float* fc2_w = (const float*)d_in[17];
    const float* fc2_b = (const float*)d_in[18];
    const float* cpd_w = (const float*)d_in[19];
    const float* cpd_b = (const float*)d_in[20];
    const float* comb_w = (const float*)d_in[21];
    const float* comb_b = (const float*)d_in[22];
    float* out = (float*)d_out;

    const int N = in_sizes[0] / 128;
    const int E = in_sizes[1] / 2;
    const int G = out_size / 2;

    const int* src = ei;
    const int* dst = ei + E;

    void *pT16, *pU16, *pA, *pB, *pDeg, *pDinv, *pRp, *pTmp, *pSums, *pFill, *pSrcs;
    cudaGetSymbolAddress(&pT16, g_h16T);
    cudaGetSymbolAddress(&pU16, g_h16U);
    cudaGetSymbolAddress(&pA, g_bufA);
    cudaGetSymbolAddress(&pB, g_bufB);
    cudaGetSymbolAddress(&pDeg, g_deg);
    cudaGetSymbolAddress(&pDinv, g_dinv);
    cudaGetSymbolAddress(&pRp, g_rowptr);
    cudaGetSymbolAddress(&pTmp, g_tmp);
    cudaGetSymbolAddress(&pSums, g_sums);
    cudaGetSymbolAddress(&pFill, g_fill);
    cudaGetSymbolAddress(&pSrcs, g_srcs);
    __half* T16 = (__half*)pT16;
    __half* U16 = (__half*)pU16;
    float* bufA = (float*)pA;
    float* bufB = (float*)pB;
    float* deg = (float*)pDeg;
    float* dinv = (float*)pDinv;
    int* rp = (int*)pRp;
    int* tmp = (int*)pTmp;
    int* sums = (int*)pSums;
    int* fill = (int*)pFill;
    int* srcs = (int*)pSrcs;

    const int TB = 256;
    const int nchunks = cdiv(N, 1024);

    // ---- degree / dinv / CSR build ----
    deg_init_kernel<<<cdiv(N, TB), TB>>>(deg, fill, N);
    deg_accum_kernel<<<cdiv(E, TB), TB>>>(dst, deg, E);
    scan_chunk_kernel<<<nchunks, 1024>>>(deg, tmp, sums, dinv, N);
    scan_sums_kernel<<<1, 256>>>(sums, nchunks);
    finalize_rowptr_kernel<<<cdiv(N, TB), TB>>>(tmp, sums, rp, N, E);
    scatter_kernel<<<cdiv(E, TB), TB>>>(src, dst, rp, fill, srcs, E);

    const int propGrid = cdiv(N, 8);  // warp per node, 8 warps/block

    // ---- encoder layer 1 (GEMM writes u-form: dinv * (x@W)) ----
    gemm_tc16_kernel<128, 128, false, true><<<cdiv(N, 64), 256>>>(x, enc_w1, T16, dinv, N);
    csr_prop_u_kernel<128, false, false><<<propGrid, TB>>>(T16, bufA, srcs, rp, dinv, enc_b1, N);

    // ---- encoder layer 2 (relu fused into GEMM A-stage; u-form out) ----
    gemm_tc16_kernel<128, 64, true, true><<<cdiv(N, 128), 256>>>(bufA, enc_w2, T16, dinv, N);
    csr_prop_u_kernel<64, false, false><<<propGrid, TB>>>(T16, bufA, srcs, rp, dinv, enc_b2, N);

    // ---- conv1 (enc2 output NOT relu'd) ----
    gemm_tc16_kernel<64, 64, false, true><<<cdiv(N, 128), 256>>>(bufA, w1, T16, dinv, N);
    csr_prop_u_kernel<64, false, false><<<propGrid, TB>>>(T16, bufA, srcs, rp, dinv, b1, N);

    // ---- conv2 ----
    gemm_tc16_kernel<64, 64, true, true><<<cdiv(N, 128), 256>>>(bufA, w2, T16, dinv, N);
    csr_prop_u_kernel<64, false, false><<<propGrid, TB>>>(T16, bufA, srcs, rp, dinv, b2, N);

    // ---- conv3 (prop writes u-form fp16, pre-relu; relu fused into SG prop1) ----
    gemm_tc16_kernel<64, 64, true, true><<<cdiv(N, 128), 256>>>(bufA, w3, T16, dinv, N);
    csr_prop_u_kernel<64, false, true><<<propGrid, TB>>>(T16, U16, srcs, rp, dinv, b3, N);

    // ---- SGConv: 4 propagations (u-form chain, last writes plain fp32) ----
    csr_prop_u_kernel<64, true, true><<<propGrid, TB>>>(U16, T16, srcs, rp, dinv, nullptr, N);
    csr_prop_u_kernel<64, false, true><<<propGrid, TB>>>(T16, U16, srcs, rp, dinv, nullptr, N);
    csr_prop_u_kernel<64, false, true><<<propGrid, TB>>>(U16, T16, srcs, rp, dinv, nullptr, N);
    csr_prop_u_kernel<64, false, false><<<propGrid, TB>>>(T16, bufA, srcs, rp, dinv, nullptr, N);

    // ---- SG linear (bias folded past max-pool; fp32 out, no scale) ----
    gemm_tc16_kernel<64, 64, false, false><<<cdiv(N, 128), 256>>>(bufA, sg_w, bufB, nullptr, N);

    // ---- fused pool + head ----
    pool_head_kernel<<<G, 256>>>(bufB, batch, sg_b, fc1_w, fc1_b, fc2_w, fc2_b,
                                 cpd_w, cpd_b, comb_w, comb_b, out, N, G);
}

// round 17
// speedup vs baseline: 1.0091x; 1.0006x over previous
#include <cuda_runtime.h>
#include <cuda_fp16.h>
#include <mma.h>
#include <cstdint>

using namespace nvcuda;

// ---------------- static scratch (no allocations allowed) ----------------
#define MAXN 100000
#define MAXE 3200000
#define MAXG 256

__device__ __half g_h16T[(size_t)MAXN * 128];  // fp16 ping (u-form features)
__device__ __half g_h16U[(size_t)MAXN * 128];  // fp16 pong
__device__ float  g_bufA[(size_t)MAXN * 128];  // prop outputs (fp32, GEMM inputs)
__device__ float  g_bufB[(size_t)MAXN * 64];   // SG linear out (fp32, pooled)
__device__ float  g_deg[MAXN];
__device__ float  g_dinv[MAXN];
__device__ int    g_rowptr[MAXN + 1];
__device__ int    g_tmp[MAXN];
__device__ int    g_sums[256];
__device__ int    g_fill[MAXN];
__device__ int    g_srcs[MAXE];  // dst-sorted src indices (4B/edge)

static inline int cdiv(long long a, int b) { return (int)((a + b - 1) / b); }

// ---------------- degree prep ----------------
__global__ void deg_init_kernel(float* __restrict__ deg, int* __restrict__ fill, int N) {
    int i = blockIdx.x * blockDim.x + threadIdx.x;
    if (i < N) { deg[i] = 1.0f; fill[i] = 0; }  // self loop
}

__global__ void deg_accum_kernel(const int* __restrict__ dst, float* __restrict__ deg, int E) {
    int e = blockIdx.x * blockDim.x + threadIdx.x;
    if (e < E) atomicAdd(&deg[dst[e]], 1.0f);
}

// ---------------- CSR build: scan of in-degree (excl self loops) + fused dinv ------------
__global__ void scan_chunk_kernel(const float* __restrict__ deg, int* __restrict__ excl,
                                  int* __restrict__ sums, float* __restrict__ dinv, int N) {
    __shared__ int sh[1024];
    int i = blockIdx.x * 1024 + threadIdx.x;
    int v = 0;
    if (i < N) {
        float d = deg[i];
        v = (int)d - 1;
        dinv[i] = rsqrtf(d);
    }
    sh[threadIdx.x] = v;
    __syncthreads();
    for (int off = 1; off < 1024; off <<= 1) {
        int add = (threadIdx.x >= off) ? sh[threadIdx.x - off] : 0;
        __syncthreads();
        sh[threadIdx.x] += add;
        __syncthreads();
    }
    if (i < N) excl[i] = sh[threadIdx.x] - v;
    if (threadIdx.x == 1023) sums[blockIdx.x] = sh[1023];
}

// finalize rowptr: each block redundantly scans the (<=256) chunk sums in smem,
// then rp[i] = excl[i] + exclusive_prefix(sums)[chunk(i)]. Kills the scan_sums launch.
__global__ void finalize_rowptr_kernel(const int* __restrict__ excl, const int* __restrict__ sums,
                                       int* __restrict__ rp, int N, int E, int nchunks) {
    __shared__ int sh[256];
    int t = threadIdx.x;  // 256
    int v = (t < nchunks) ? sums[t] : 0;
    sh[t] = v;
    __syncthreads();
    for (int off = 1; off < 256; off <<= 1) {
        int add = (t >= off) ? sh[t - off] : 0;
        __syncthreads();
        sh[t] += add;
        __syncthreads();
    }
    // sh[c] is inclusive; exclusive prefix of chunk c = sh[c] - sums[c]
    int i = blockIdx.x * blockDim.x + t;
    if (i < N) {
        int c = i >> 10;
        rp[i] = excl[i] + sh[c] - sums[c];
    }
    if (i == 0) rp[N] = E;
}

__global__ void scatter_kernel(const int* __restrict__ src, const int* __restrict__ dst,
                               const int* __restrict__ rp, int* __restrict__ fill,
                               int* __restrict__ srcs, int E) {
    int e = blockIdx.x * blockDim.x + threadIdx.x;
    if (e >= E) return;
    int d = dst[e];
    int pos = rp[d] + atomicAdd(&fill[d], 1);
    srcs[pos] = src[e];
}

// ---------------- split-fp16 tensor-core GEMM (3x HMMA, ~fp32 precision) ----------------
// OUT[N,DOUT] = act(A)[N,DIN] @ W[DIN,DOUT]; A fp32, split hi/lo at staging.
// If dscale != nullptr, output row scaled by dscale[row] (u-form for props).
template <int DIN, int DOUT, bool RELU_IN, bool OUT_HALF>
__global__ __launch_bounds__(256) void gemm_tc16_kernel(const float* __restrict__ A,
                                                        const float* __restrict__ W,
                                                        void* __restrict__ outv,
                                                        const float* __restrict__ dscale,
                                                        int N) {
    constexpr int TR = (DOUT == 128) ? 64 : 128;
    constexpr int KC = 32;
    constexpr int AH = KC + 8;
    constexpr int WHD = DOUT + 8;
    constexpr int WP = DOUT + 4;
    constexpr int WC = DOUT / 32;
    constexpr int NT = 256;
    constexpr int B_AH = TR * AH * 2;
    constexpr int B_WH = KC * WHD * 2;
    constexpr int B_TILES = 2 * B_AH + 2 * B_WH;
    constexpr int B_STAGE = TR * WP * 4;
    constexpr int SMB = (B_TILES > B_STAGE) ? B_TILES : B_STAGE;
    __shared__ __align__(16) char smraw[SMB];
    __half* Ah = (__half*)smraw;
    __half* Al = (__half*)(smraw + B_AH);
    __half* Wh = (__half*)(smraw + 2 * B_AH);
    __half* Wl = (__half*)(smraw + 2 * B_AH + B_WH);

    const int tid = threadIdx.x;
    const int wid = tid >> 5;
    const int wr = wid / WC;
    const int wc = wid % WC;
    const int rbase = blockIdx.x * TR;

    wmma::fragment<wmma::accumulator, 16, 16, 16, float> c[2][2];
#pragma unroll
    for (int r = 0; r < 2; r++)
#pragma unroll
        for (int j = 0; j < 2; j++) wmma::fill_fragment(c[r][j], 0.0f);

    for (int k0 = 0; k0 < DIN; k0 += KC) {
        for (int idx = tid; idx < TR * KC / 4; idx += NT) {
            int r = idx / (KC / 4);
            int c4 = (idx % (KC / 4)) * 4;
            float4 v = make_float4(0.f, 0.f, 0.f, 0.f);
            int gr = rbase + r;
            if (gr < N) v = *(const float4*)(A + (size_t)gr * DIN + k0 + c4);
            if (RELU_IN) {
                v.x = fmaxf(v.x, 0.f); v.y = fmaxf(v.y, 0.f);
                v.z = fmaxf(v.z, 0.f); v.w = fmaxf(v.w, 0.f);
            }
            __half hx = __float2half_rn(v.x), hy = __float2half_rn(v.y);
            __half hz = __float2half_rn(v.z), hw = __float2half_rn(v.w);
            __half lx = __float2half_rn(v.x - __half2float(hx));
            __half ly = __float2half_rn(v.y - __half2float(hy));
            __half lz = __float2half_rn(v.z - __half2float(hz));
            __half lw = __float2half_rn(v.w - __half2float(hw));
            *(__half2*)(Ah + r * AH + c4) = __halves2half2(hx, hy);
            *(__half2*)(Ah + r * AH + c4 + 2) = __halves2half2(hz, hw);
            *(__half2*)(Al + r * AH + c4) = __halves2half2(lx, ly);
            *(__half2*)(Al + r * AH + c4 + 2) = __halves2half2(lz, lw);
        }
        for (int idx = tid; idx < KC * DOUT / 4; idx += NT) {
            int r = idx / (DOUT / 4);
            int c4 = (idx % (DOUT / 4)) * 4;
            float4 v = *(const float4*)(W + (size_t)(k0 + r) * DOUT + c4);
            __half hx = __float2half_rn(v.x), hy = __float2half_rn(v.y);
            __half hz = __float2half_rn(v.z), hw = __float2half_rn(v.w);
            __half lx = __float2half_rn(v.x - __half2float(hx));
            __half ly = __float2half_rn(v.y - __half2float(hy));
            __half lz = __float2half_rn(v.z - __half2float(hz));
            __half lw = __float2half_rn(v.w - __half2float(hw));
            *(__half2*)(Wh + r * WHD + c4) = __halves2half2(hx, hy);
            *(__half2*)(Wh + r * WHD + c4 + 2) = __halves2half2(hz, hw);
            *(__half2*)(Wl + r * WHD + c4) = __halves2half2(lx, ly);
            *(__half2*)(Wl + r * WHD + c4 + 2) = __halves2half2(lz, lw);
        }
        __syncthreads();

#pragma unroll
        for (int ks = 0; ks < KC; ks += 16) {
            wmma::fragment<wmma::matrix_a, 16, 16, 16, __half, wmma::row_major> ah[2], al[2];
            wmma::fragment<wmma::matrix_b, 16, 16, 16, __half, wmma::row_major> bh[2], bl[2];
#pragma unroll
            for (int r = 0; r < 2; r++) {
                wmma::load_matrix_sync(ah[r], Ah + (wr * 32 + r * 16) * AH + ks, AH);
                wmma::load_matrix_sync(al[r], Al + (wr * 32 + r * 16) * AH + ks, AH);
            }
#pragma unroll
            for (int j = 0; j < 2; j++) {
                wmma::load_matrix_sync(bh[j], Wh + ks * WHD + wc * 32 + j * 16, WHD);
                wmma::load_matrix_sync(bl[j], Wl + ks * WHD + wc * 32 + j * 16, WHD);
            }
#pragma unroll
            for (int r = 0; r < 2; r++)
#pragma unroll
                for (int j = 0; j < 2; j++) {
                    wmma::mma_sync(c[r][j], al[r], bh[j], c[r][j]);
                    wmma::mma_sync(c[r][j], ah[r], bl[j], c[r][j]);
                    wmma::mma_sync(c[r][j], ah[r], bh[j], c[r][j]);
                }
        }
        __syncthreads();
    }

    float* stage = (float*)smraw;
#pragma unroll
    for (int r = 0; r < 2; r++)
#pragma unroll
        for (int j = 0; j < 2; j++)
            wmma::store_matrix_sync(stage + (wr * 32 + r * 16) * WP + wc * 32 + j * 16,
                                    c[r][j], WP, wmma::mem_row_major);
    __syncthreads();

    for (int idx = tid; idx < TR * DOUT / 4; idx += NT) {
        int r = idx / (DOUT / 4);
        int c4 = (idx % (DOUT / 4)) * 4;
        int gr = rbase + r;
        if (gr >= N) continue;
        float4 v = *(float4*)(stage + r * WP + c4);
        float sc = dscale ? dscale[gr] : 1.0f;
        v.x *= sc; v.y *= sc; v.z *= sc; v.w *= sc;
        if constexpr (OUT_HALF) {
            __half* out = (__half*)outv;
            __half2 ha = __floats2half2_rn(v.x, v.y);
            __half2 hb = __floats2half2_rn(v.z, v.w);
            uint2 u;
            u.x = *(unsigned*)&ha;
            u.y = *(unsigned*)&hb;
            *(uint2*)(out + (size_t)gr * DOUT + c4) = u;
        } else {
            *(float4*)((float*)outv + (size_t)gr * DOUT + c4) = v;
        }
    }
}

// ---------------- CSR propagate on u-form features ----------------
// u[s] = dinv[s]*t[s] stored fp16. out_i = dinv_i*(act(u_i) + sum_j act(u_src_j)) + b.
// SCALE_OUT: write fp16(dinv_i * out_i) (u-form for next prop); else fp32 plain.
template <int D, bool RELU, bool SCALE_OUT>
__global__ void csr_prop_u_kernel(const __half* __restrict__ t, void* __restrict__ outv,
                                  const int* __restrict__ srcs, const int* __restrict__ rp,
                                  const float* __restrict__ dinv, const float* __restrict__ bias,
                                  int N) {
    constexpr int H = D / 32;
    int warp = (blockIdx.x * blockDim.x + threadIdx.x) >> 5;
    int lane = threadIdx.x & 31;
    if (warp >= N) return;
    const int i = warp;
    int j0 = rp[i], j1 = rp[i + 1];

    float acc[H];
#pragma unroll
    for (int v = 0; v < H; v++) acc[v] = 0.f;

    auto load_row = [&](int s, float* f) {
        if constexpr (H == 2) {
            unsigned u = *((const unsigned*)(t + (size_t)s * D) + lane);
            float2 fv = __half22float2(*(__half2*)&u);
            f[0] = fv.x; f[1] = fv.y;
        } else {
            uint2 u = *((const uint2*)(t + (size_t)s * D) + lane);
            float2 fa = __half22float2(*(__half2*)&u.x);
            float2 fb = __half22float2(*(__half2*)&u.y);
            f[0] = fa.x; f[1] = fa.y; f[2] = fb.x; f[3] = fb.y;
        }
    };

    int j = j0;
    for (; j + 7 < j1; j += 8) {
        int s[8];
#pragma unroll
        for (int u = 0; u < 8; u++) s[u] = srcs[j + u];
        float a[8][H > 2 ? 4 : 2];
#pragma unroll
        for (int u = 0; u < 8; u++) load_row(s[u], a[u]);
#pragma unroll
        for (int u = 0; u < 8; u++)
#pragma unroll
            for (int v = 0; v < H; v++)
                acc[v] += RELU ? fmaxf(a[u][v], 0.f) : a[u][v];
    }
    for (; j + 1 < j1; j += 2) {
        int s0 = srcs[j], s1 = srcs[j + 1];
        float a0[H], a1[H];
        load_row(s0, a0);
        load_row(s1, a1);
#pragma unroll
        for (int v = 0; v < H; v++) {
            acc[v] += RELU ? fmaxf(a0[v], 0.f) : a0[v];
            acc[v] += RELU ? fmaxf(a1[v], 0.f) : a1[v];
        }
    }
    if (j < j1) {
        int s0 = srcs[j];
        float a0[H];
        load_row(s0, a0);
#pragma unroll
        for (int v = 0; v < H; v++) acc[v] += RELU ? fmaxf(a0[v], 0.f) : a0[v];
    }

    float dv = dinv[i];
    float self[H];
    load_row(i, self);
    float o[H];
#pragma unroll
    for (int v = 0; v < H; v++) {
        float sv = RELU ? fmaxf(self[v], 0.f) : self[v];
        float b = bias ? bias[lane * H + v] : 0.f;
        o[v] = fmaf(dv, acc[v] + sv, b);
        if (SCALE_OUT) o[v] *= dv;
    }

    if constexpr (SCALE_OUT) {
        __half* out = (__half*)outv;
        if constexpr (H == 2) {
            __half2 h = __floats2half2_rn(o[0], o[1]);
            *((unsigned*)(out + (size_t)i * D) + lane) = *(unsigned*)&h;
        } else {
            __half2 ha = __floats2half2_rn(o[0], o[1]);
            __half2 hb = __floats2half2_rn(o[2], o[3]);
            uint2 u;
            u.x = *(unsigned*)&ha;
            u.y = *(unsigned*)&hb;
            *((uint2*)(out + (size_t)i * D) + lane) = u;
        }
    } else {
        float* out = (float*)outv;
        if constexpr (H == 2) {
            *(float2*)(out + (size_t)i * D + lane * 2) = make_float2(o[0], o[1]);
        } else {
            *(float4*)(out + (size_t)i * D + lane * 4) = make_float4(o[0], o[1], o[2], o[3]);
        }
    }
}

// ---------------- fused segment-bounds + max-pool + head MLP (one block per graph) -------
__global__ void pool_head_kernel(const float* __restrict__ z, const int* __restrict__ batch,
                                 const float* __restrict__ sgb,
                                 const float* __restrict__ fc1w, const float* __restrict__ fc1b,
                                 const float* __restrict__ fc2w, const float* __restrict__ fc2b,
                                 const float* __restrict__ cpdw, const float* __restrict__ cpdb,
                                 const float* __restrict__ combw, const float* __restrict__ combb,
                                 float* __restrict__ out, int N, int G) {
    int g = blockIdx.x;
    int t = threadIdx.x;  // 256
    int tx = t & 63;
    int ty = t >> 6;      // 0..3
    __shared__ int se[2];
    __shared__ float sm[4][64];
    __shared__ float z0[64], z1[32], z2[16];

    if (t < 2) {
        int target = g + t;
        int lo = 0, hi = N;
        while (lo < hi) {
            int mid = (lo + hi) >> 1;
            if (batch[mid] < target) lo = mid + 1; else hi = mid;
        }
        se[t] = lo;
    }
    __syncthreads();
    int s = se[0], e = se[1];

    float m = -3.4028235e38f;
    for (int i = s + ty; i < e; i += 4) m = fmaxf(m, z[(size_t)i * 64 + tx]);
    sm[ty][tx] = m;
    __syncthreads();
    if (ty == 0)
        z0[tx] = fmaxf(fmaxf(sm[0][tx], sm[1][tx]), fmaxf(sm[2][tx], sm[3][tx])) + sgb[tx];
    __syncthreads();

    if (t < 32) {
        float sacc = fc1b[t];
        for (int k = 0; k < 64; k++) sacc = fmaf(z0[k], fc1w[k * 32 + t], sacc);
        z1[t] = fmaxf(sacc, 0.f);
    }
    __syncthreads();
    if (t < 16) {
        float sacc = fc2b[t];
        for (int k = 0; k < 32; k++) sacc = fmaf(z1[k], fc2w[k * 16 + t], sacc);
        z2[t] = fmaxf(sacc, 0.f);
    }
    __syncthreads();
    if (t == 0) {
        float sacc = cpdb[0];
        for (int k = 0; k < 16; k++) sacc = fmaf(z2[k], cpdw[k], sacc);
        out[g] = sacc;
    }
    if (t == 1) {
        float sacc = combb[0];
        for (int k = 0; k < 16; k++) sacc = fmaf(z2[k], combw[k], sacc);
        out[G + g] = sacc;
    }
}

// ---------------- host side ----------------
extern "C" void kernel_launch(void* const* d_in, const int* in_sizes, int n_in,
                              void* d_out, int out_size) {
    const float* x     = (const float*)d_in[0];
    const int*   ei    = (const int*)d_in[1];
    const int*   batch = (const int*)d_in[2];
    const float* enc_w1 = (const float*)d_in[3];
    const float* enc_b1 = (const float*)d_in[4];
    const float* enc_w2 = (const float*)d_in[5];
    const float* enc_b2 = (const float*)d_in[6];
    const float* w1 = (const float*)d_in[7];
    const float* b1 = (const float*)d_in[8];
    const float* w2 = (const float*)d_in[9];
    const float* b2 = (const float*)d_in[10];
    const float* w3 = (const float*)d_in[11];
    const float* b3 = (const float*)d_in[12];
    const float* sg_w = (const float*)d_in[13];
    const float* sg_b = (const float*)d_in[14];
    const float* fc1_w = (const float*)d_in[15];
    const float* fc1_b = (const float*)d_in[16];
    const float* fc2_w = (const float*)d_in[17];
    const float* fc2_b = (const float*)d_in[18];
    const float* cpd_w = (const float*)d_in[19];
    const float* cpd_b = (const float*)d_in[20];
    const float* comb_w = (const float*)d_in[21];
    const float* comb_b = (const float*)d_in[22];
    float* out = (float*)d_out;

    const int N = in_sizes[0] / 128;
    const int E = in_sizes[1] / 2;
    const int G = out_size / 2;

    const int* src = ei;
    const int* dst = ei + E;

    void *pT16, *pU16, *pA, *pB, *pDeg, *pDinv, *pRp, *pTmp, *pSums, *pFill, *pSrcs;
    cudaGetSymbolAddress(&pT16, g_h16T);
    cudaGetSymbolAddress(&pU16, g_h16U);
    cudaGetSymbolAddress(&pA, g_bufA);
    cudaGetSymbolAddress(&pB, g_bufB);
    cudaGetSymbolAddress(&pDeg, g_deg);
    cudaGetSymbolAddress(&pDinv, g_dinv);
    cudaGetSymbolAddress(&pRp, g_rowptr);
    cudaGetSymbolAddress(&pTmp, g_tmp);
    cudaGetSymbolAddress(&pSums, g_sums);
    cudaGetSymbolAddress(&pFill, g_fill);
    cudaGetSymbolAddress(&pSrcs, g_srcs);
    __half* T16 = (__half*)pT16;
    __half* U16 = (__half*)pU16;
    float* bufA = (float*)pA;
    float* bufB = (float*)pB;
    float* deg = (float*)pDeg;
    float* dinv = (float*)pDinv;
    int* rp = (int*)pRp;
    int* tmp = (int*)pTmp;
    int* sums = (int*)pSums;
    int* fill = (int*)pFill;
    int* srcs = (int*)pSrcs;

    const int TB = 256;
    const int nchunks = cdiv(N, 1024);

    // ---- degree / dinv / CSR build (scan_sums fused into finalize) ----
    deg_init_kernel<<<cdiv(N, TB), TB>>>(deg, fill, N);
    deg_accum_kernel<<<cdiv(E, TB), TB>>>(dst, deg, E);
    scan_chunk_kernel<<<nchunks, 1024>>>(deg, tmp, sums, dinv, N);
    finalize_rowptr_kernel<<<cdiv(N, TB), TB>>>(tmp, sums, rp, N, E, nchunks);
    scatter_kernel<<<cdiv(E, TB), TB>>>(src, dst, rp, fill, srcs, E);

    const int propGrid = cdiv(N, 8);  // warp per node, 8 warps/block

    // ---- encoder layer 1 (GEMM writes u-form: dinv * (x@W)) ----
    gemm_tc16_kernel<128, 128, false, true><<<cdiv(N, 64), 256>>>(x, enc_w1, T16, dinv, N);
    csr_prop_u_kernel<128, false, false><<<propGrid, TB>>>(T16, bufA, srcs, rp, dinv, enc_b1, N);

    // ---- encoder layer 2 (relu fused into GEMM A-stage; u-form out) ----
    gemm_tc16_kernel<128, 64, true, true><<<cdiv(N, 128), 256>>>(bufA, enc_w2, T16, dinv, N);
    csr_prop_u_kernel<64, false, false><<<propGrid, TB>>>(T16, bufA, srcs, rp, dinv, enc_b2, N);

    // ---- conv1 (enc2 output NOT relu'd) ----
    gemm_tc16_kernel<64, 64, false, true><<<cdiv(N, 128), 256>>>(bufA, w1, T16, dinv, N);
    csr_prop_u_kernel<64, false, false><<<propGrid, TB>>>(T16, bufA, srcs, rp, dinv, b1, N);

    // ---- conv2 ----
    gemm_tc16_kernel<64, 64, true, true><<<cdiv(N, 128), 256>>>(bufA, w2, T16, dinv, N);
    csr_prop_u_kernel<64, false, false><<<propGrid, TB>>>(T16, bufA, srcs, rp, dinv, b2, N);

    // ---- conv3 (prop writes u-form fp16, pre-relu; relu fused into SG prop1) ----
    gemm_tc16_kernel<64, 64, true, true><<<cdiv(N, 128), 256>>>(bufA, w3, T16, dinv, N);
    csr_prop_u_kernel<64, false, true><<<propGrid, TB>>>(T16, U16, srcs, rp, dinv, b3, N);

    // ---- SGConv: 4 propagations (u-form chain, last writes plain fp32) ----
    csr_prop_u_kernel<64, true, true><<<propGrid, TB>>>(U16, T16, srcs, rp, dinv, nullptr, N);
    csr_prop_u_kernel<64, false, true><<<propGrid, TB>>>(T16, U16, srcs, rp, dinv, nullptr, N);
    csr_prop_u_kernel<64, false, true><<<propGrid, TB>>>(U16, T16, srcs, rp, dinv, nullptr, N);
    csr_prop_u_kernel<64, false, false><<<propGrid, TB>>>(T16, bufA, srcs, rp, dinv, nullptr, N);

    // ---- SG linear (bias folded past max-pool; fp32 out, no scale) ----
    gemm_tc16_kernel<64, 64, false, false><<<cdiv(N, 128), 256>>>(bufA, sg_w, bufB, nullptr, N);

    // ---- fused pool + head ----
    pool_head_kernel<<<G, 256>>>(bufB, batch, sg_b, fc1_w, fc1_b, fc2_w, fc2_b,
                                 cpd_w, cpd_b, comb_w, comb_b, out, N, G);
}